// round 1
// baseline (speedup 1.0000x reference)
#include <cuda_runtime.h>
#include <math.h>

#define G 2
#define NN 50000
#define NE 800000
#define ET (NE + NN)   // edges + self loops = 850000

// ---------------- scratch (device globals; no allocation allowed) ----------------
__device__ float        g_h1[(size_t)G * NN * 256];   // layer1 transformed features
__device__ float        g_agg1[(size_t)G * NN * 256]; // layer1 aggregation / layer2 input
__device__ float        g_h2[(size_t)G * NN * 128];   // layer2 transformed features
__device__ float        g_als[G * NN * 4];            // alpha-src logits (reused layer2, H=1)
__device__ float        g_ald[G * NN * 4];
__device__ unsigned int g_mkey[G * NN * 4];           // segment-max keys
__device__ float        g_s[G * NN * 4];              // segment softmax denominators
__device__ float        g_ex[(size_t)G * ET * 4];     // per-edge logits -> exp values

// ---------------- helpers ----------------
__device__ __forceinline__ unsigned fkey(float f) {
    unsigned u = __float_as_uint(f);
    return (u & 0x80000000u) ? ~u : (u | 0x80000000u);
}
__device__ __forceinline__ float funkey(unsigned k) {
    unsigned u = (k & 0x80000000u) ? (k & 0x7FFFFFFFu) : ~k;
    return __uint_as_float(u);
}
// vectorized global reduction (sm_90+): 1 LTS op per 16B instead of 4
__device__ __forceinline__ void red4(float* p, float a, float b, float c, float d) {
    asm volatile("red.global.add.v4.f32 [%0], {%1,%2,%3,%4};"
                 :: "l"(p), "f"(a), "f"(b), "f"(c), "f"(d) : "memory");
}

// ---------------- GEMM: Out[g][N][M] = X[g][N][K] @ W[g][K][M] ----------------
// BM=128, BN=64, BK=16, 256 threads, each computes 8x4
template <int K, int M>
__global__ void gemm_kernel(const float* __restrict__ X, const float* __restrict__ W,
                            float* __restrict__ O) {
    __shared__ float As[16][128];
    __shared__ float Bs[16][64];
    const int g = blockIdx.z;
    const float* Xg = X + (size_t)g * NN * K;
    const float* Wg = W + (size_t)g * K * M;
    float* Og = O + (size_t)g * NN * M;
    const int row0 = blockIdx.x * 128;
    const int col0 = blockIdx.y * 64;
    const int tid = threadIdx.x;
    const int tr = (tid >> 4) << 3;   // 0..120
    const int tc = (tid & 15) << 2;   // 0..60
    float acc[8][4];
#pragma unroll
    for (int i = 0; i < 8; i++)
#pragma unroll
        for (int j = 0; j < 4; j++) acc[i][j] = 0.f;

    const int ar = tid >> 2;          // 0..63
    const int ak = (tid & 3) << 2;    // 0,4,8,12
    const int bk = tid >> 4;          // 0..15
    const int bc = (tid & 15) << 2;   // 0..60

    for (int k0 = 0; k0 < K; k0 += 16) {
#pragma unroll
        for (int rr = 0; rr < 128; rr += 64) {
            int row = row0 + ar + rr;
            float4 v = make_float4(0.f, 0.f, 0.f, 0.f);
            if (row < NN) v = *(const float4*)&Xg[(size_t)row * K + k0 + ak];
            As[ak + 0][ar + rr] = v.x;
            As[ak + 1][ar + rr] = v.y;
            As[ak + 2][ar + rr] = v.z;
            As[ak + 3][ar + rr] = v.w;
        }
        *(float4*)&Bs[bk][bc] = *(const float4*)&Wg[(size_t)(k0 + bk) * M + col0 + bc];
        __syncthreads();
#pragma unroll
        for (int kk = 0; kk < 16; kk++) {
            float4 b = *(const float4*)&Bs[kk][tc];
            float a[8];
#pragma unroll
            for (int i = 0; i < 8; i++) a[i] = As[kk][tr + i];
#pragma unroll
            for (int i = 0; i < 8; i++) {
                acc[i][0] += a[i] * b.x;
                acc[i][1] += a[i] * b.y;
                acc[i][2] += a[i] * b.z;
                acc[i][3] += a[i] * b.w;
            }
        }
        __syncthreads();
    }
#pragma unroll
    for (int i = 0; i < 8; i++) {
        int row = row0 + tr + i;
        if (row < NN) {
            float4 r = make_float4(acc[i][0], acc[i][1], acc[i][2], acc[i][3]);
            *(float4*)&Og[(size_t)row * M + col0 + tc] = r;
        }
    }
}

// ---------------- per-node attention logits: al = <h[n,h,:], a[h,:]> ----------------
template <int H, int C>
__global__ void al_kernel(const float* __restrict__ hbuf, const float* __restrict__ a_src,
                          const float* __restrict__ a_dst, float* __restrict__ als,
                          float* __restrict__ ald) {
    int idx = blockIdx.x * blockDim.x + threadIdx.x;  // (g*NN+n)*H + h
    if (idx >= G * NN * H) return;
    int h = idx % H;
    int gn = idx / H;
    int g = gn / NN;
    const float* hp = hbuf + (size_t)gn * (H * C) + h * C;
    const float* as = a_src + (g * H + h) * C;
    const float* ad = a_dst + (g * H + h) * C;
    float s1 = 0.f, s2 = 0.f;
#pragma unroll
    for (int c = 0; c < C; c += 4) {
        float4 hv = *(const float4*)(hp + c);
        float4 av = *(const float4*)(as + c);
        float4 dv = *(const float4*)(ad + c);
        s1 += hv.x * av.x + hv.y * av.y + hv.z * av.z + hv.w * av.w;
        s2 += hv.x * dv.x + hv.y * dv.y + hv.z * dv.z + hv.w * dv.w;
    }
    als[idx] = s1;
    ald[idx] = s2;
}

// ---------------- zero-init kernels ----------------
__global__ void zero_l1_kernel() {
    size_t i = (size_t)blockIdx.x * blockDim.x + threadIdx.x;
    size_t stride = (size_t)gridDim.x * blockDim.x;
    for (size_t j = i; j < (size_t)G * NN * 4; j += stride) {
        g_mkey[j] = 0u;
        g_s[j] = 0.f;
    }
    for (size_t j = i; j < (size_t)G * NN * 256; j += stride) g_agg1[j] = 0.f;
}
__global__ void zero_l2_kernel(float* __restrict__ out) {
    size_t i = (size_t)blockIdx.x * blockDim.x + threadIdx.x;
    size_t stride = (size_t)gridDim.x * blockDim.x;
    for (size_t j = i; j < (size_t)G * NN; j += stride) {
        g_mkey[j] = 0u;
        g_s[j] = 0.f;
    }
    for (size_t j = i; j < (size_t)G * NN * 128; j += stride) out[j] = 0.f;
}

// ---------------- edge pass 1: logits + segment max ----------------
template <int H>
__global__ void edge_logit_kernel(const int* __restrict__ ei, const float* __restrict__ als,
                                  const float* __restrict__ ald, float* __restrict__ exbuf,
                                  unsigned int* __restrict__ mkey) {
    int idx = blockIdx.x * blockDim.x + threadIdx.x;
    if (idx >= G * ET) return;
    int g = idx / ET, e = idx % ET;
    int src, dst;
    if (e < NE) {
        src = ei[(size_t)g * 2 * NE + e];
        dst = ei[(size_t)g * 2 * NE + NE + e];
    } else {
        src = dst = e - NE;
    }
#pragma unroll
    for (int h = 0; h < H; h++) {
        float v = als[(g * NN + src) * H + h] + ald[(g * NN + dst) * H + h];
        v = v > 0.f ? v : 0.2f * v;  // leaky relu, slope 0.2
        exbuf[(size_t)idx * H + h] = v;
        atomicMax(&mkey[(g * NN + dst) * H + h], fkey(v));
    }
}

// ---------------- edge pass 2: exp + segment sum ----------------
template <int H>
__global__ void edge_exp_kernel(const int* __restrict__ ei, float* __restrict__ exbuf,
                                const unsigned int* __restrict__ mkey,
                                float* __restrict__ sbuf) {
    int idx = blockIdx.x * blockDim.x + threadIdx.x;
    if (idx >= G * ET) return;
    int g = idx / ET, e = idx % ET;
    int dst;
    if (e < NE) dst = ei[(size_t)g * 2 * NE + NE + e];
    else dst = e - NE;
#pragma unroll
    for (int h = 0; h < H; h++) {
        float ev = exbuf[(size_t)idx * H + h];
        float m = funkey(mkey[(g * NN + dst) * H + h]);
        float p = expf(ev - m);
        exbuf[(size_t)idx * H + h] = p;
        atomicAdd(&sbuf[(g * NN + dst) * H + h], p);
    }
}

// ---------------- edge pass 3: weighted aggregation (warp per edge) ----------------
template <int H, int C>
__global__ void edge_agg_kernel(const int* __restrict__ ei, const float* __restrict__ hbuf,
                                const float* __restrict__ exbuf, const float* __restrict__ sbuf,
                                float* __restrict__ agg) {
    int wid = (blockIdx.x * blockDim.x + threadIdx.x) >> 5;
    int lane = threadIdx.x & 31;
    if (wid >= G * ET) return;
    int g = wid / ET, e = wid % ET;
    int src, dst;
    if (e < NE) {
        src = ei[(size_t)g * 2 * NE + e];
        dst = ei[(size_t)g * 2 * NE + NE + e];
    } else {
        src = dst = e - NE;
    }
    constexpr int F = H * C;
    constexpr int PER = F / 32;  // 8 (layer1) or 4 (layer2) floats per lane
    int f0 = lane * PER;
    int h = f0 / C;
    float alpha = exbuf[(size_t)wid * H + h] / sbuf[(g * NN + dst) * H + h];
    const float* hp = hbuf + (size_t)(g * NN + src) * F + f0;
    float* op = agg + (size_t)(g * NN + dst) * F + f0;
#pragma unroll
    for (int c = 0; c < PER; c += 4) {
        float4 v = *(const float4*)(hp + c);
        red4(op + c, v.x * alpha, v.y * alpha, v.z * alpha, v.w * alpha);
    }
}

// ---------------- bias + ELU ----------------
template <int F>
__global__ void bias_elu_kernel(const float* __restrict__ in, const float* __restrict__ bias,
                                float* __restrict__ out) {
    int idx = blockIdx.x * blockDim.x + threadIdx.x;  // over G*NN*(F/4)
    if (idx >= G * NN * (F / 4)) return;
    int q = idx % (F / 4);
    int gn = idx / (F / 4);
    int g = gn / NN;
    float4 v = *(const float4*)(in + (size_t)gn * F + q * 4);
    float4 b = *(const float4*)(bias + g * F + q * 4);
    v.x += b.x; v.y += b.y; v.z += b.z; v.w += b.w;
    v.x = v.x > 0.f ? v.x : expm1f(v.x);
    v.y = v.y > 0.f ? v.y : expm1f(v.y);
    v.z = v.z > 0.f ? v.z : expm1f(v.z);
    v.w = v.w > 0.f ? v.w : expm1f(v.w);
    *(float4*)(out + (size_t)gn * F + q * 4) = v;
}

// ---------------- host ----------------
static inline int ceil_div(int a, int b) { return (a + b - 1) / b; }

extern "C" void kernel_launch(void* const* d_in, const int* in_sizes, int n_in,
                              void* d_out, int out_size) {
    const float* x   = (const float*)d_in[0];
    const int*   ei  = (const int*)d_in[1];
    const float* W1  = (const float*)d_in[2];
    const float* a1s = (const float*)d_in[3];
    const float* a1d = (const float*)d_in[4];
    const float* b1  = (const float*)d_in[5];
    const float* W2  = (const float*)d_in[6];
    const float* a2s = (const float*)d_in[7];
    const float* a2d = (const float*)d_in[8];
    const float* b2  = (const float*)d_in[9];
    float* out = (float*)d_out;

    float *h1, *agg1, *h2, *als, *ald, *sb, *exb;
    unsigned int* mk;
    cudaGetSymbolAddress((void**)&h1, g_h1);
    cudaGetSymbolAddress((void**)&agg1, g_agg1);
    cudaGetSymbolAddress((void**)&h2, g_h2);
    cudaGetSymbolAddress((void**)&als, g_als);
    cudaGetSymbolAddress((void**)&ald, g_ald);
    cudaGetSymbolAddress((void**)&sb, g_s);
    cudaGetSymbolAddress((void**)&exb, g_ex);
    cudaGetSymbolAddress((void**)&mk, g_mkey);

    const int TPB = 256;
    const int nrow_blocks = ceil_div(NN, 128);  // 391

    // ---- Layer 1: heads=4, C=64 ----
    gemm_kernel<128, 256><<<dim3(nrow_blocks, 256 / 64, G), TPB>>>(x, W1, h1);
    al_kernel<4, 64><<<ceil_div(G * NN * 4, TPB), TPB>>>(h1, a1s, a1d, als, ald);
    zero_l1_kernel<<<2048, TPB>>>();
    edge_logit_kernel<4><<<ceil_div(G * ET, TPB), TPB>>>(ei, als, ald, exb, mk);
    edge_exp_kernel<4><<<ceil_div(G * ET, TPB), TPB>>>(ei, exb, mk, sb);
    edge_agg_kernel<4, 64><<<ceil_div(G * ET * 32, TPB), TPB>>>(ei, h1, exb, sb, agg1);
    bias_elu_kernel<256><<<ceil_div(G * NN * 64, TPB), TPB>>>(agg1, b1, agg1);

    // ---- Layer 2: heads=1, C=128 ----
    gemm_kernel<256, 128><<<dim3(nrow_blocks, 128 / 64, G), TPB>>>(agg1, W2, h2);
    al_kernel<1, 128><<<ceil_div(G * NN, TPB), TPB>>>(h2, a2s, a2d, als, ald);
    zero_l2_kernel<<<2048, TPB>>>(out);
    edge_logit_kernel<1><<<ceil_div(G * ET, TPB), TPB>>>(ei, als, ald, exb, mk);
    edge_exp_kernel<1><<<ceil_div(G * ET, TPB), TPB>>>(ei, exb, mk, sb);
    edge_agg_kernel<1, 128><<<ceil_div(G * ET * 32, TPB), TPB>>>(ei, h2, exb, sb, out);
    bias_elu_kernel<128><<<ceil_div(G * NN * 32, TPB), TPB>>>(out, b2, out);
}

// round 2
// speedup vs baseline: 1.6976x; 1.6976x over previous
#include <cuda_runtime.h>
#include <math.h>

#define G 2
#define NN 50000
#define NE 800000
#define M_NODES (G * NN)          // 100000
#define SCAN_BLK 1024
#define NBLK ((M_NODES + SCAN_BLK - 1) / SCAN_BLK)   // 98

// ---------------- scratch (device globals) ----------------
__device__ float g_h1[(size_t)G * NN * 256];    // layer1 transformed features
__device__ float g_agg1[(size_t)G * NN * 256];  // layer1 output / layer2 input
__device__ float g_h2[(size_t)G * NN * 128];    // layer2 transformed features
__device__ float g_als[G * NN * 4];
__device__ float g_ald[G * NN * 4];
__device__ int   g_cnt[M_NODES];                // per-node in-degree
__device__ int   g_rowptr[M_NODES + 1];
__device__ int   g_fill[M_NODES];
__device__ int   g_col[G * NE];                 // CSR: src node per incoming edge
__device__ int   g_bsum[256];                   // block sums for scan
__device__ int   g_bpre[256];                   // block prefix

// ---------------- GEMM: Out[g][N][M] = X[g][N][K] @ W[g][K][M] ----------------
template <int K, int M>
__global__ void gemm_kernel(const float* __restrict__ X, const float* __restrict__ W,
                            float* __restrict__ O) {
    __shared__ float As[16][128];
    __shared__ float Bs[16][64];
    const int g = blockIdx.z;
    const float* Xg = X + (size_t)g * NN * K;
    const float* Wg = W + (size_t)g * K * M;
    float* Og = O + (size_t)g * NN * M;
    const int row0 = blockIdx.x * 128;
    const int col0 = blockIdx.y * 64;
    const int tid = threadIdx.x;
    const int tr = (tid >> 4) << 3;
    const int tc = (tid & 15) << 2;
    float acc[8][4];
#pragma unroll
    for (int i = 0; i < 8; i++)
#pragma unroll
        for (int j = 0; j < 4; j++) acc[i][j] = 0.f;

    const int ar = tid >> 2;
    const int ak = (tid & 3) << 2;
    const int bk = tid >> 4;
    const int bc = (tid & 15) << 2;

    for (int k0 = 0; k0 < K; k0 += 16) {
#pragma unroll
        for (int rr = 0; rr < 128; rr += 64) {
            int row = row0 + ar + rr;
            float4 v = make_float4(0.f, 0.f, 0.f, 0.f);
            if (row < NN) v = *(const float4*)&Xg[(size_t)row * K + k0 + ak];
            As[ak + 0][ar + rr] = v.x;
            As[ak + 1][ar + rr] = v.y;
            As[ak + 2][ar + rr] = v.z;
            As[ak + 3][ar + rr] = v.w;
        }
        *(float4*)&Bs[bk][bc] = *(const float4*)&Wg[(size_t)(k0 + bk) * M + col0 + bc];
        __syncthreads();
#pragma unroll
        for (int kk = 0; kk < 16; kk++) {
            float4 b = *(const float4*)&Bs[kk][tc];
            float a[8];
#pragma unroll
            for (int i = 0; i < 8; i++) a[i] = As[kk][tr + i];
#pragma unroll
            for (int i = 0; i < 8; i++) {
                acc[i][0] += a[i] * b.x;
                acc[i][1] += a[i] * b.y;
                acc[i][2] += a[i] * b.z;
                acc[i][3] += a[i] * b.w;
            }
        }
        __syncthreads();
    }
#pragma unroll
    for (int i = 0; i < 8; i++) {
        int row = row0 + tr + i;
        if (row < NN) {
            float4 r = make_float4(acc[i][0], acc[i][1], acc[i][2], acc[i][3]);
            *(float4*)&Og[(size_t)row * M + col0 + tc] = r;
        }
    }
}

// ---------------- per-node attention logits ----------------
template <int H, int C>
__global__ void al_kernel(const float* __restrict__ hbuf, const float* __restrict__ a_src,
                          const float* __restrict__ a_dst, float* __restrict__ als,
                          float* __restrict__ ald) {
    int idx = blockIdx.x * blockDim.x + threadIdx.x;
    if (idx >= G * NN * H) return;
    int h = idx % H;
    int gn = idx / H;
    int g = gn / NN;
    const float* hp = hbuf + (size_t)gn * (H * C) + h * C;
    const float* as = a_src + (g * H + h) * C;
    const float* ad = a_dst + (g * H + h) * C;
    float s1 = 0.f, s2 = 0.f;
#pragma unroll
    for (int c = 0; c < C; c += 4) {
        float4 hv = *(const float4*)(hp + c);
        float4 av = *(const float4*)(as + c);
        float4 dv = *(const float4*)(ad + c);
        s1 += hv.x * av.x + hv.y * av.y + hv.z * av.z + hv.w * av.w;
        s2 += hv.x * dv.x + hv.y * dv.y + hv.z * dv.z + hv.w * dv.w;
    }
    als[idx] = s1;
    ald[idx] = s2;
}

// ---------------- CSR build ----------------
__global__ void csr_zero_kernel() {
    int i = blockIdx.x * blockDim.x + threadIdx.x;
    if (i < M_NODES) g_cnt[i] = 0;
}
__global__ void csr_hist_kernel(const int* __restrict__ ei) {
    int idx = blockIdx.x * blockDim.x + threadIdx.x;
    if (idx >= G * NE) return;
    int g = idx / NE, e = idx % NE;
    int dst = ei[(size_t)g * 2 * NE + NE + e];
    atomicAdd(&g_cnt[g * NN + dst], 1);
}
__global__ void csr_scanA_kernel() {
    __shared__ int sh[SCAN_BLK];
    int i = blockIdx.x * SCAN_BLK + threadIdx.x;
    int v = (i < M_NODES) ? g_cnt[i] : 0;
    sh[threadIdx.x] = v;
    __syncthreads();
#pragma unroll
    for (int off = 1; off < SCAN_BLK; off <<= 1) {
        int t = (threadIdx.x >= off) ? sh[threadIdx.x - off] : 0;
        __syncthreads();
        sh[threadIdx.x] += t;
        __syncthreads();
    }
    if (i < M_NODES) g_rowptr[i] = sh[threadIdx.x] - v;  // exclusive within block
    if (threadIdx.x == SCAN_BLK - 1) g_bsum[blockIdx.x] = sh[SCAN_BLK - 1];
}
__global__ void csr_scanB_kernel() {
    if (threadIdx.x == 0) {
        int run = 0;
        for (int b = 0; b < NBLK; b++) {
            g_bpre[b] = run;
            run += g_bsum[b];
        }
        g_rowptr[M_NODES] = run;  // == G*NE
    }
}
__global__ void csr_scanC_kernel() {
    int i = blockIdx.x * blockDim.x + threadIdx.x;
    if (i >= M_NODES) return;
    int v = g_rowptr[i] + g_bpre[i / SCAN_BLK];
    g_rowptr[i] = v;
    g_fill[i] = v;
}
__global__ void csr_scatter_kernel(const int* __restrict__ ei) {
    int idx = blockIdx.x * blockDim.x + threadIdx.x;
    if (idx >= G * NE) return;
    int g = idx / NE, e = idx % NE;
    int src = ei[(size_t)g * 2 * NE + e];
    int dst = ei[(size_t)g * 2 * NE + NE + e];
    int pos = atomicAdd(&g_fill[g * NN + dst], 1);
    g_col[pos] = src;
}

// ---------------- fused softmax + aggregation + bias + ELU (warp per dst node) ----------------
__device__ __forceinline__ float lrelu(float v) { return v > 0.f ? v : 0.2f * v; }

template <int H, int C>
__global__ void node_agg_kernel(const float* __restrict__ als, const float* __restrict__ ald,
                                const float* __restrict__ hbuf, const float* __restrict__ bias,
                                float* __restrict__ out) {
    int wid = (blockIdx.x * blockDim.x + threadIdx.x) >> 5;
    int lane = threadIdx.x & 31;
    if (wid >= M_NODES) return;
    int g = wid / NN;
    const int gbase = g * NN;

    int rbeg = g_rowptr[wid];
    int deg = g_rowptr[wid + 1] - rbeg;

    float aldh[H], selfv[H], mx[H];
#pragma unroll
    for (int h = 0; h < H; h++) {
        aldh[h] = ald[wid * H + h];
        selfv[h] = lrelu(als[wid * H + h] + aldh[h]);
        mx[h] = selfv[h];
    }
    // pass 1: max over incoming edges
    for (int i = lane; i < deg; i += 32) {
        int src = g_col[rbeg + i];
#pragma unroll
        for (int h = 0; h < H; h++)
            mx[h] = fmaxf(mx[h], lrelu(als[(gbase + src) * H + h] + aldh[h]));
    }
#pragma unroll
    for (int h = 0; h < H; h++) {
#pragma unroll
        for (int off = 16; off > 0; off >>= 1)
            mx[h] = fmaxf(mx[h], __shfl_xor_sync(0xFFFFFFFFu, mx[h], off));
    }
    // pass 2: sum of exp
    float sm[H];
#pragma unroll
    for (int h = 0; h < H; h++) sm[h] = (lane == 0) ? expf(selfv[h] - mx[h]) : 0.f;
    for (int i = lane; i < deg; i += 32) {
        int src = g_col[rbeg + i];
#pragma unroll
        for (int h = 0; h < H; h++)
            sm[h] += expf(lrelu(als[(gbase + src) * H + h] + aldh[h]) - mx[h]);
    }
#pragma unroll
    for (int h = 0; h < H; h++) {
#pragma unroll
        for (int off = 16; off > 0; off >>= 1)
            sm[h] += __shfl_xor_sync(0xFFFFFFFFu, sm[h], off);
    }
    // pass 3: aggregate (warp-cooperative over features; serial over edges)
    constexpr int F = H * C;
    constexpr int PER = F / 32;  // 8 (layer1) / 4 (layer2)
    const int f0 = lane * PER;
    const int myh = f0 / C;
    const float inv_s = 1.f / sm[myh];
    const float mymx = mx[myh];
    const float myald = aldh[myh];

    float acc[PER];
    {
        float a_self = expf(selfv[myh] - mymx) * inv_s;
        const float* hp = hbuf + (size_t)wid * F + f0;
#pragma unroll
        for (int c = 0; c < PER; c += 4) {
            float4 v = *(const float4*)(hp + c);
            acc[c + 0] = v.x * a_self;
            acc[c + 1] = v.y * a_self;
            acc[c + 2] = v.z * a_self;
            acc[c + 3] = v.w * a_self;
        }
    }
    for (int i = 0; i < deg; i++) {
        int src = g_col[rbeg + i];
        float alpha = expf(lrelu(als[(gbase + src) * H + myh] + myald) - mymx) * inv_s;
        const float* hp = hbuf + (size_t)(gbase + src) * F + f0;
#pragma unroll
        for (int c = 0; c < PER; c += 4) {
            float4 v = *(const float4*)(hp + c);
            acc[c + 0] += v.x * alpha;
            acc[c + 1] += v.y * alpha;
            acc[c + 2] += v.z * alpha;
            acc[c + 3] += v.w * alpha;
        }
    }
    // bias + ELU, single store
    float* op = out + (size_t)wid * F + f0;
    const float* bp = bias + g * F + f0;
#pragma unroll
    for (int c = 0; c < PER; c++) {
        float v = acc[c] + bp[c];
        op[c] = v > 0.f ? v : expm1f(v);
    }
}

// ---------------- host ----------------
static inline int ceil_div(int a, int b) { return (a + b - 1) / b; }

extern "C" void kernel_launch(void* const* d_in, const int* in_sizes, int n_in,
                              void* d_out, int out_size) {
    const float* x   = (const float*)d_in[0];
    const int*   ei  = (const int*)d_in[1];
    const float* W1  = (const float*)d_in[2];
    const float* a1s = (const float*)d_in[3];
    const float* a1d = (const float*)d_in[4];
    const float* b1  = (const float*)d_in[5];
    const float* W2  = (const float*)d_in[6];
    const float* a2s = (const float*)d_in[7];
    const float* a2d = (const float*)d_in[8];
    const float* b2  = (const float*)d_in[9];
    float* out = (float*)d_out;

    float *h1, *agg1, *h2, *als, *ald;
    cudaGetSymbolAddress((void**)&h1, g_h1);
    cudaGetSymbolAddress((void**)&agg1, g_agg1);
    cudaGetSymbolAddress((void**)&h2, g_h2);
    cudaGetSymbolAddress((void**)&als, g_als);
    cudaGetSymbolAddress((void**)&ald, g_ald);

    const int TPB = 256;
    const int nrow_blocks = ceil_div(NN, 128);

    // ---- CSR build (shared by both layers) ----
    csr_zero_kernel<<<ceil_div(M_NODES, TPB), TPB>>>();
    csr_hist_kernel<<<ceil_div(G * NE, TPB), TPB>>>(ei);
    csr_scanA_kernel<<<NBLK, SCAN_BLK>>>();
    csr_scanB_kernel<<<1, 32>>>();
    csr_scanC_kernel<<<ceil_div(M_NODES, TPB), TPB>>>();
    csr_scatter_kernel<<<ceil_div(G * NE, TPB), TPB>>>(ei);

    // ---- Layer 1: heads=4, C=64 ----
    gemm_kernel<128, 256><<<dim3(nrow_blocks, 256 / 64, G), TPB>>>(x, W1, h1);
    al_kernel<4, 64><<<ceil_div(G * NN * 4, TPB), TPB>>>(h1, a1s, a1d, als, ald);
    node_agg_kernel<4, 64><<<ceil_div(M_NODES * 32, TPB), TPB>>>(als, ald, h1, b1, agg1);

    // ---- Layer 2: heads=1, C=128 ----
    gemm_kernel<256, 128><<<dim3(nrow_blocks, 128 / 64, G), TPB>>>(agg1, W2, h2);
    al_kernel<1, 128><<<ceil_div(G * NN, TPB), TPB>>>(h2, a2s, a2d, als, ald);
    node_agg_kernel<1, 128><<<ceil_div(M_NODES * 32, TPB), TPB>>>(als, ald, h2, b2, out);
}

// round 7
// speedup vs baseline: 1.8784x; 1.1065x over previous
#include <cuda_runtime.h>
#include <math.h>

#define G 2
#define NN 50000
#define NE 800000
#define M_NODES (G * NN)          // 100000
#define SCAN_BLK 1024
#define NBLK ((M_NODES + SCAN_BLK - 1) / SCAN_BLK)   // 98

// ---------------- scratch (device globals) ----------------
__device__ float g_h1[(size_t)G * NN * 256];    // layer1 transformed features
__device__ float g_agg1[(size_t)G * NN * 256];  // layer1 output / layer2 input
__device__ float g_h2[(size_t)G * NN * 128];    // layer2 transformed features
__device__ float g_als[G * NN * 4];
__device__ float g_ald[G * NN * 4];
__device__ int   g_cnt[M_NODES];
__device__ int   g_rowptr[M_NODES + 1];
__device__ int   g_fill[M_NODES];
__device__ int   g_col[G * NE];
__device__ int   g_bsum[256];
__device__ int   g_bpre[256];

// ---------------- GEMM: O[g][N][M] = X[g][N][K] @ W[g][K][M] ----------------
// 128x128 tile, BK=16, 256 threads, 8x8 per thread (2x2 of 4x4), double-buffered smem.
template <int K, int M>
__global__ void __launch_bounds__(256, 2) gemm_kernel(const float* __restrict__ X,
                                                      const float* __restrict__ W,
                                                      float* __restrict__ O) {
    __shared__ float As[2][16][128];
    __shared__ float Bs[2][16][128];
    const int g = blockIdx.z;
    const float* Xg = X + (size_t)g * NN * K;
    const float* Wg = W + (size_t)g * K * M;
    float* Og = O + (size_t)g * NN * M;
    const int row0 = blockIdx.x * 128;
    const int col0 = blockIdx.y * 128;
    const int tid = threadIdx.x;
    const int tx = tid & 15;        // col group 0..15
    const int ty = tid >> 4;        // row group 0..15

    const int arow = tid >> 2;        // 0..63 (two rounds: +0, +64)
    const int ak   = (tid & 3) * 4;   // 0,4,8,12
    const int bk   = tid >> 4;        // 0..15
    const int bcol = (tid & 15) * 4;  // 0..60 (two rounds: +0, +64)

    float acc[8][8];
#pragma unroll
    for (int i = 0; i < 8; i++)
#pragma unroll
        for (int j = 0; j < 8; j++) acc[i][j] = 0.f;

    float4 a0, a1, b0, b1;
    // prologue: load k-slice 0
    {
        int row = row0 + arow;
        a0 = make_float4(0.f, 0.f, 0.f, 0.f);
        a1 = a0;
        if (row < NN)      a0 = *(const float4*)&Xg[(size_t)row * K + ak];
        if (row + 64 < NN) a1 = *(const float4*)&Xg[(size_t)(row + 64) * K + ak];
        b0 = *(const float4*)&Wg[(size_t)bk * M + col0 + bcol];
        b1 = *(const float4*)&Wg[(size_t)bk * M + col0 + bcol + 64];
    }
    // store stage 0 (A transposed)
    As[0][ak + 0][arow] = a0.x; As[0][ak + 1][arow] = a0.y;
    As[0][ak + 2][arow] = a0.z; As[0][ak + 3][arow] = a0.w;
    As[0][ak + 0][arow + 64] = a1.x; As[0][ak + 1][arow + 64] = a1.y;
    As[0][ak + 2][arow + 64] = a1.z; As[0][ak + 3][arow + 64] = a1.w;
    *(float4*)&Bs[0][bk][bcol]      = b0;
    *(float4*)&Bs[0][bk][bcol + 64] = b1;
    __syncthreads();

    for (int k0 = 0; k0 < K; k0 += 16) {
        const int buf = (k0 >> 4) & 1;
        const bool more = (k0 + 16) < K;
        if (more) {
            int kn = k0 + 16;
            int row = row0 + arow;
            a0 = make_float4(0.f, 0.f, 0.f, 0.f);
            a1 = a0;
            if (row < NN)      a0 = *(const float4*)&Xg[(size_t)row * K + kn + ak];
            if (row + 64 < NN) a1 = *(const float4*)&Xg[(size_t)(row + 64) * K + kn + ak];
            b0 = *(const float4*)&Wg[(size_t)(kn + bk) * M + col0 + bcol];
            b1 = *(const float4*)&Wg[(size_t)(kn + bk) * M + col0 + bcol + 64];
        }
#pragma unroll
        for (int kk = 0; kk < 16; kk++) {
            float ar[8], br[8];
            *(float4*)(ar)     = *(const float4*)&As[buf][kk][ty * 4];
            *(float4*)(ar + 4) = *(const float4*)&As[buf][kk][64 + ty * 4];
            *(float4*)(br)     = *(const float4*)&Bs[buf][kk][tx * 4];
            *(float4*)(br + 4) = *(const float4*)&Bs[buf][kk][64 + tx * 4];
#pragma unroll
            for (int i = 0; i < 8; i++)
#pragma unroll
                for (int j = 0; j < 8; j++) acc[i][j] += ar[i] * br[j];
        }
        if (more) {
            const int nb = buf ^ 1;
            As[nb][ak + 0][arow] = a0.x; As[nb][ak + 1][arow] = a0.y;
            As[nb][ak + 2][arow] = a0.z; As[nb][ak + 3][arow] = a0.w;
            As[nb][ak + 0][arow + 64] = a1.x; As[nb][ak + 1][arow + 64] = a1.y;
            As[nb][ak + 2][arow + 64] = a1.z; As[nb][ak + 3][arow + 64] = a1.w;
            *(float4*)&Bs[nb][bk][bcol]      = b0;
            *(float4*)&Bs[nb][bk][bcol + 64] = b1;
        }
        __syncthreads();
    }

#pragma unroll
    for (int i = 0; i < 8; i++) {
        int row = row0 + ((i < 4) ? (ty * 4 + i) : (64 + ty * 4 + i - 4));
        if (row < NN) {
            float4 v0 = make_float4(acc[i][0], acc[i][1], acc[i][2], acc[i][3]);
            float4 v1 = make_float4(acc[i][4], acc[i][5], acc[i][6], acc[i][7]);
            *(float4*)&Og[(size_t)row * M + col0 + tx * 4]      = v0;
            *(float4*)&Og[(size_t)row * M + col0 + 64 + tx * 4] = v1;
        }
    }
}

// ---------------- per-node attention logits ----------------
template <int H, int C>
__global__ void al_kernel(const float* __restrict__ hbuf, const float* __restrict__ a_src,
                          const float* __restrict__ a_dst, float* __restrict__ als,
                          float* __restrict__ ald) {
    int idx = blockIdx.x * blockDim.x + threadIdx.x;
    if (idx >= G * NN * H) return;
    int h = idx % H;
    int gn = idx / H;
    int g = gn / NN;
    const float* hp = hbuf + (size_t)gn * (H * C) + h * C;
    const float* as = a_src + (g * H + h) * C;
    const float* ad = a_dst + (g * H + h) * C;
    float s1 = 0.f, s2 = 0.f;
#pragma unroll
    for (int c = 0; c < C; c += 4) {
        float4 hv = *(const float4*)(hp + c);
        float4 av = *(const float4*)(as + c);
        float4 dv = *(const float4*)(ad + c);
        s1 += hv.x * av.x + hv.y * av.y + hv.z * av.z + hv.w * av.w;
        s2 += hv.x * dv.x + hv.y * dv.y + hv.z * dv.z + hv.w * dv.w;
    }
    als[idx] = s1;
    ald[idx] = s2;
}

// ---------------- CSR build ----------------
__global__ void csr_zero_kernel() {
    int i = blockIdx.x * blockDim.x + threadIdx.x;
    if (i < M_NODES) g_cnt[i] = 0;
}
__global__ void csr_hist_kernel(const int* __restrict__ ei) {
    int idx = blockIdx.x * blockDim.x + threadIdx.x;
    if (idx >= G * NE) return;
    int g = idx / NE, e = idx % NE;
    int dst = ei[(size_t)g * 2 * NE + NE + e];
    atomicAdd(&g_cnt[g * NN + dst], 1);
}
__global__ void csr_scanA_kernel() {
    __shared__ int sh[SCAN_BLK];
    int i = blockIdx.x * SCAN_BLK + threadIdx.x;
    int v = (i < M_NODES) ? g_cnt[i] : 0;
    sh[threadIdx.x] = v;
    __syncthreads();
#pragma unroll
    for (int off = 1; off < SCAN_BLK; off <<= 1) {
        int t = (threadIdx.x >= off) ? sh[threadIdx.x - off] : 0;
        __syncthreads();
        sh[threadIdx.x] += t;
        __syncthreads();
    }
    if (i < M_NODES) g_rowptr[i] = sh[threadIdx.x] - v;
    if (threadIdx.x == SCAN_BLK - 1) g_bsum[blockIdx.x] = sh[SCAN_BLK - 1];
}
__global__ void csr_scanB_kernel() {
    __shared__ int sh[128];
    int t = threadIdx.x;
    int v = (t < NBLK) ? g_bsum[t] : 0;
    sh[t] = v;
    __syncthreads();
#pragma unroll
    for (int off = 1; off < 128; off <<= 1) {
        int u = (t >= off) ? sh[t - off] : 0;
        __syncthreads();
        sh[t] += u;
        __syncthreads();
    }
    if (t < NBLK) g_bpre[t] = sh[t] - v;
    if (t == 127) g_rowptr[M_NODES] = sh[127];
}
__global__ void csr_scanC_kernel() {
    int i = blockIdx.x * blockDim.x + threadIdx.x;
    if (i >= M_NODES) return;
    int v = g_rowptr[i] + g_bpre[i / SCAN_BLK];
    g_rowptr[i] = v;
    g_fill[i] = v;
}
__global__ void csr_scatter_kernel(const int* __restrict__ ei) {
    int idx = blockIdx.x * blockDim.x + threadIdx.x;
    if (idx >= G * NE) return;
    int g = idx / NE, e = idx % NE;
    int src = ei[(size_t)g * 2 * NE + e];
    int dst = ei[(size_t)g * 2 * NE + NE + e];
    int pos = atomicAdd(&g_fill[g * NN + dst], 1);
    g_col[pos] = src;
}

// ---------------- fused online-softmax + aggregation + bias + ELU (warp per dst node) ----------------
__device__ __forceinline__ float lrelu(float v) { return v > 0.f ? v : 0.2f * v; }

template <int H, int C>
__global__ void node_agg_kernel(const float* __restrict__ als, const float* __restrict__ ald,
                                const float* __restrict__ hbuf, const float* __restrict__ bias,
                                float* __restrict__ out) {
    int wid = (blockIdx.x * blockDim.x + threadIdx.x) >> 5;
    int lane = threadIdx.x & 31;
    if (wid >= M_NODES) return;
    int g = wid / NN;
    const int gbase = g * NN;

    int rbeg = g_rowptr[wid];
    int deg = g_rowptr[wid + 1] - rbeg;

    // single online-softmax pass over incoming edges (self-loop seeded on lane 0)
    float aldh[H], m[H], s[H];
#pragma unroll
    for (int h = 0; h < H; h++) {
        aldh[h] = ald[wid * H + h];
        float selfv = lrelu(als[wid * H + h] + aldh[h]);
        m[h] = (lane == 0) ? selfv : -1e30f;
        s[h] = (lane == 0) ? 1.f : 0.f;
    }
    for (int i = lane; i < deg; i += 32) {
        int src = g_col[rbeg + i];
#pragma unroll
        for (int h = 0; h < H; h++) {
            float e = lrelu(als[(gbase + src) * H + h] + aldh[h]);
            float mn = fmaxf(m[h], e);
            s[h] = s[h] * __expf(m[h] - mn) + __expf(e - mn);
            m[h] = mn;
        }
    }
#pragma unroll
    for (int h = 0; h < H; h++) {
#pragma unroll
        for (int off = 16; off > 0; off >>= 1) {
            float mo = __shfl_xor_sync(0xFFFFFFFFu, m[h], off);
            float so = __shfl_xor_sync(0xFFFFFFFFu, s[h], off);
            float mn = fmaxf(m[h], mo);
            s[h] = s[h] * __expf(m[h] - mn) + so * __expf(mo - mn);
            m[h] = mn;
        }
    }

    constexpr int F = H * C;
    constexpr int PER = F / 32;  // 8 (layer1) / 4 (layer2)
    const int f0 = lane * PER;
    const int myh = f0 / C;
    const float inv_s = 1.f / s[myh];
    const float mymx = m[myh];
    const float myald = aldh[myh];

    float acc[PER];
    {
        float selfv = lrelu(als[wid * H + myh] + myald);
        float a_self = __expf(selfv - mymx) * inv_s;
        const float* hp = hbuf + (size_t)wid * F + f0;
#pragma unroll
        for (int c = 0; c < PER; c += 4) {
            float4 v = *(const float4*)(hp + c);
            acc[c + 0] = v.x * a_self;
            acc[c + 1] = v.y * a_self;
            acc[c + 2] = v.z * a_self;
            acc[c + 3] = v.w * a_self;
        }
    }
    for (int i = 0; i < deg; i++) {
        int src = g_col[rbeg + i];
        float alpha = __expf(lrelu(als[(gbase + src) * H + myh] + myald) - mymx) * inv_s;
        const float* hp = hbuf + (size_t)(gbase + src) * F + f0;
#pragma unroll
        for (int c = 0; c < PER; c += 4) {
            float4 v = *(const float4*)(hp + c);
            acc[c + 0] += v.x * alpha;
            acc[c + 1] += v.y * alpha;
            acc[c + 2] += v.z * alpha;
            acc[c + 3] += v.w * alpha;
        }
    }
    float* op = out + (size_t)wid * F + f0;
    const float* bp = bias + g * F + f0;
#pragma unroll
    for (int c = 0; c < PER; c++) {
        float v = acc[c] + bp[c];
        op[c] = v > 0.f ? v : expm1f(v);
    }
}

// ---------------- host ----------------
static inline int ceil_div(int a, int b) { return (a + b - 1) / b; }

extern "C" void kernel_launch(void* const* d_in, const int* in_sizes, int n_in,
                              void* d_out, int out_size) {
    const float* x   = (const float*)d_in[0];
    const int*   ei  = (const int*)d_in[1];
    const float* W1  = (const float*)d_in[2];
    const float* a1s = (const float*)d_in[3];
    const float* a1d = (const float*)d_in[4];
    const float* b1  = (const float*)d_in[5];
    const float* W2  = (const float*)d_in[6];
    const float* a2s = (const float*)d_in[7];
    const float* a2d = (const float*)d_in[8];
    const float* b2  = (const float*)d_in[9];
    float* out = (float*)d_out;

    float *h1, *agg1, *h2, *als, *ald;
    cudaGetSymbolAddress((void**)&h1, g_h1);
    cudaGetSymbolAddress((void**)&agg1, g_agg1);
    cudaGetSymbolAddress((void**)&h2, g_h2);
    cudaGetSymbolAddress((void**)&als, g_als);
    cudaGetSymbolAddress((void**)&ald, g_ald);

    const int TPB = 256;
    const int nrow_blocks = ceil_div(NN, 128);  // 391

    // order chosen so the ncu capture window (~4th launch) lands on gemm1
    csr_zero_kernel<<<ceil_div(M_NODES, TPB), TPB>>>();
    csr_hist_kernel<<<ceil_div(G * NE, TPB), TPB>>>(ei);
    csr_scanA_kernel<<<NBLK, SCAN_BLK>>>();
    gemm_kernel<128, 256><<<dim3(nrow_blocks, 2, G), TPB>>>(x, W1, h1);
    csr_scanB_kernel<<<1, 128>>>();
    csr_scanC_kernel<<<ceil_div(M_NODES, TPB), TPB>>>();
    csr_scatter_kernel<<<ceil_div(G * NE, TPB), TPB>>>(ei);

    // ---- Layer 1: heads=4, C=64 ----
    al_kernel<4, 64><<<ceil_div(G * NN * 4, TPB), TPB>>>(h1, a1s, a1d, als, ald);
    node_agg_kernel<4, 64><<<ceil_div(M_NODES * 32, TPB), TPB>>>(als, ald, h1, b1, agg1);

    // ---- Layer 2: heads=1, C=128 ----
    gemm_kernel<256, 128><<<dim3(nrow_blocks, 1, G), TPB>>>(agg1, W2, h2);
    al_kernel<1, 128><<<ceil_div(G * NN, TPB), TPB>>>(h2, a2s, a2d, als, ald);
    node_agg_kernel<1, 128><<<ceil_div(M_NODES * 32, TPB), TPB>>>(als, ald, h2, b2, out);
}

// round 9
// speedup vs baseline: 2.1142x; 1.1255x over previous
#include <cuda_runtime.h>
#include <cuda_bf16.h>
#include <mma.h>
#include <math.h>

typedef unsigned int u32;
typedef unsigned long long u64;
using namespace nvcuda;

#define G 2
#define NN 50000
#define NE 800000
#define M_NODES (G * NN)          // 100000
#define SCAN_BLK 1024
#define NBLK ((M_NODES + SCAN_BLK - 1) / SCAN_BLK)   // 98

// ---------------- scratch (device globals) ----------------
__device__ float          g_h1[(size_t)G * NN * 256];   // layer1 transformed (f32)
__device__ float          g_h2[(size_t)G * NN * 128];   // layer2 transformed (f32)
__device__ __nv_bfloat16  g_xhi[(size_t)G * NN * 128];  // x split
__device__ __nv_bfloat16  g_xlo[(size_t)G * NN * 128];
__device__ __nv_bfloat16  g_a1hi[(size_t)G * NN * 256]; // layer1 output split (GEMM2 input)
__device__ __nv_bfloat16  g_a1lo[(size_t)G * NN * 256];
__device__ __nv_bfloat16  g_w1hi[G * 128 * 256];        // W1 split, native [K][M]
__device__ __nv_bfloat16  g_w1lo[G * 128 * 256];
__device__ __nv_bfloat16  g_w2hi[G * 256 * 128];        // W2 split, native [K][M]
__device__ __nv_bfloat16  g_w2lo[G * 256 * 128];
__device__ float          g_als[G * NN * 4];
__device__ float          g_ald[G * NN * 4];
__device__ int            g_cnt[M_NODES];
__device__ int            g_rowptr[M_NODES + 1];
__device__ int            g_fill[M_NODES];
__device__ int            g_col[G * NE];
__device__ int            g_bsum[256];
__device__ int            g_bpre[256];

// ---------------- WMMA GEMM: O[g][N][M] = A[g][N][K] @ W[g][K][M], bf16x3, f32 accum ----------
// block 128x128, BK=32, 8 warps each 32x64. Double-buffered dynamic smem, register staging.
#define AS_LD 40              // A smem row stride (elements), pad vs bank conflicts
#define BS_LD 136             // B smem row stride
#define ASZ (128 * AS_LD * 2) // bytes per A sub-buffer (10240)
#define BSZ (32 * BS_LD * 2)  // bytes per B sub-buffer (8704)
#define STAGE_B (2 * ASZ + 2 * BSZ)  // 37888
#define SMEM_TOT (2 * STAGE_B)       // 75776

template <int K, int M>
__global__ void __launch_bounds__(256, 2) gemm_wmma_kernel(
    const __nv_bfloat16* __restrict__ Ahi, const __nv_bfloat16* __restrict__ Alo,
    const __nv_bfloat16* __restrict__ Bhi, const __nv_bfloat16* __restrict__ Blo,
    float* __restrict__ O) {
    extern __shared__ char sm[];
    const int g = blockIdx.z;
    const int row0 = blockIdx.x * 128;
    const int col0 = blockIdx.y * 128;
    const int tid = threadIdx.x;
    const int wid = tid >> 5;
    const int wm = (wid & 3) * 32;        // warp row offset in tile
    const int wn = (wid >> 2) * 64;       // warp col offset in tile

    const __nv_bfloat16* Ah = Ahi + (size_t)g * NN * K;
    const __nv_bfloat16* Al = Alo + (size_t)g * NN * K;
    const __nv_bfloat16* Bh = Bhi + (size_t)g * K * M;
    const __nv_bfloat16* Bl = Blo + (size_t)g * K * M;

    // per-thread staging indices: A tile 128x32 = 512 uint4 per sub-buffer (2/thread)
    const int ar0 = tid >> 2, ac0 = (tid & 3);            // row, k8-group
    const int ar1 = (tid + 256) >> 2, ac1 = ((tid + 256) & 3);
    // B tile 32x128 = 512 uint4 (2/thread)
    const int bk0 = tid >> 4, bn0 = (tid & 15);
    const int bk1 = (tid + 256) >> 4, bn1 = ((tid + 256) & 15);

    wmma::fragment<wmma::accumulator, 16, 16, 16, float> acc[2][4];
#pragma unroll
    for (int i = 0; i < 2; i++)
#pragma unroll
        for (int n = 0; n < 4; n++) wmma::fill_fragment(acc[i][n], 0.f);

    uint4 rah0, rah1, ral0, ral1, rbh0, rbh1, rbl0, rbl1;

    const int NSTAGE = K / 32;
    // prologue: stage 0 -> regs -> buf0
    {
        const int ks = 0;
        rah0 = make_uint4(0, 0, 0, 0); ral0 = rah0; rah1 = rah0; ral1 = rah0;
        if (row0 + ar0 < NN) {
            size_t o = (size_t)(row0 + ar0) * K + ks + ac0 * 8;
            rah0 = *(const uint4*)(Ah + o); ral0 = *(const uint4*)(Al + o);
        }
        if (row0 + ar1 < NN) {
            size_t o = (size_t)(row0 + ar1) * K + ks + ac1 * 8;
            rah1 = *(const uint4*)(Ah + o); ral1 = *(const uint4*)(Al + o);
        }
        size_t ob0 = (size_t)(ks + bk0) * M + col0 + bn0 * 8;
        size_t ob1 = (size_t)(ks + bk1) * M + col0 + bn1 * 8;
        rbh0 = *(const uint4*)(Bh + ob0); rbl0 = *(const uint4*)(Bl + ob0);
        rbh1 = *(const uint4*)(Bh + ob1); rbl1 = *(const uint4*)(Bl + ob1);
        char* base = sm;
        *(uint4*)(base + ar0 * (AS_LD * 2) + ac0 * 16) = rah0;
        *(uint4*)(base + ar1 * (AS_LD * 2) + ac1 * 16) = rah1;
        *(uint4*)(base + ASZ + ar0 * (AS_LD * 2) + ac0 * 16) = ral0;
        *(uint4*)(base + ASZ + ar1 * (AS_LD * 2) + ac1 * 16) = ral1;
        *(uint4*)(base + 2 * ASZ + bk0 * (BS_LD * 2) + bn0 * 16) = rbh0;
        *(uint4*)(base + 2 * ASZ + bk1 * (BS_LD * 2) + bn1 * 16) = rbh1;
        *(uint4*)(base + 2 * ASZ + BSZ + bk0 * (BS_LD * 2) + bn0 * 16) = rbl0;
        *(uint4*)(base + 2 * ASZ + BSZ + bk1 * (BS_LD * 2) + bn1 * 16) = rbl1;
    }
    __syncthreads();

    for (int st = 0; st < NSTAGE; st++) {
        const int buf = st & 1;
        const bool more = (st + 1) < NSTAGE;
        if (more) {
            const int ks = (st + 1) * 32;
            rah0 = make_uint4(0, 0, 0, 0); ral0 = rah0; rah1 = rah0; ral1 = rah0;
            if (row0 + ar0 < NN) {
                size_t o = (size_t)(row0 + ar0) * K + ks + ac0 * 8;
                rah0 = *(const uint4*)(Ah + o); ral0 = *(const uint4*)(Al + o);
            }
            if (row0 + ar1 < NN) {
                size_t o = (size_t)(row0 + ar1) * K + ks + ac1 * 8;
                rah1 = *(const uint4*)(Ah + o); ral1 = *(const uint4*)(Al + o);
            }
            size_t ob0 = (size_t)(ks + bk0) * M + col0 + bn0 * 8;
            size_t ob1 = (size_t)(ks + bk1) * M + col0 + bn1 * 8;
            rbh0 = *(const uint4*)(Bh + ob0); rbl0 = *(const uint4*)(Bl + ob0);
            rbh1 = *(const uint4*)(Bh + ob1); rbl1 = *(const uint4*)(Bl + ob1);
        }
        // compute 2 k16 steps from buf
        {
            const __nv_bfloat16* pAh = (const __nv_bfloat16*)(sm + buf * STAGE_B);
            const __nv_bfloat16* pAl = (const __nv_bfloat16*)(sm + buf * STAGE_B + ASZ);
            const __nv_bfloat16* pBh = (const __nv_bfloat16*)(sm + buf * STAGE_B + 2 * ASZ);
            const __nv_bfloat16* pBl = (const __nv_bfloat16*)(sm + buf * STAGE_B + 2 * ASZ + BSZ);
#pragma unroll
            for (int kk = 0; kk < 32; kk += 16) {
                wmma::fragment<wmma::matrix_a, 16, 16, 16, __nv_bfloat16, wmma::row_major> afh[2], afl[2];
#pragma unroll
                for (int i = 0; i < 2; i++) {
                    wmma::load_matrix_sync(afh[i], pAh + (wm + i * 16) * AS_LD + kk, AS_LD);
                    wmma::load_matrix_sync(afl[i], pAl + (wm + i * 16) * AS_LD + kk, AS_LD);
                }
#pragma unroll
                for (int n = 0; n < 4; n++) {
                    wmma::fragment<wmma::matrix_b, 16, 16, 16, __nv_bfloat16, wmma::row_major> bfh, bfl;
                    wmma::load_matrix_sync(bfh, pBh + kk * BS_LD + wn + n * 16, BS_LD);
                    wmma::load_matrix_sync(bfl, pBl + kk * BS_LD + wn + n * 16, BS_LD);
#pragma unroll
                    for (int i = 0; i < 2; i++) {
                        wmma::mma_sync(acc[i][n], afh[i], bfh, acc[i][n]);
                        wmma::mma_sync(acc[i][n], afh[i], bfl, acc[i][n]);
                        wmma::mma_sync(acc[i][n], afl[i], bfh, acc[i][n]);
                    }
                }
            }
        }
        if (more) {
            char* base = sm + (buf ^ 1) * STAGE_B;
            *(uint4*)(base + ar0 * (AS_LD * 2) + ac0 * 16) = rah0;
            *(uint4*)(base + ar1 * (AS_LD * 2) + ac1 * 16) = rah1;
            *(uint4*)(base + ASZ + ar0 * (AS_LD * 2) + ac0 * 16) = ral0;
            *(uint4*)(base + ASZ + ar1 * (AS_LD * 2) + ac1 * 16) = ral1;
            *(uint4*)(base + 2 * ASZ + bk0 * (BS_LD * 2) + bn0 * 16) = rbh0;
            *(uint4*)(base + 2 * ASZ + bk1 * (BS_LD * 2) + bn1 * 16) = rbh1;
            *(uint4*)(base + 2 * ASZ + BSZ + bk0 * (BS_LD * 2) + bn0 * 16) = rbl0;
            *(uint4*)(base + 2 * ASZ + BSZ + bk1 * (BS_LD * 2) + bn1 * 16) = rbl1;
        }
        __syncthreads();
    }

    // epilogue: NN % 16 == 0, so per-frag row guard is exact
#pragma unroll
    for (int i = 0; i < 2; i++) {
        int rbase = row0 + wm + i * 16;
        if (rbase < NN) {
            float* op = O + (size_t)g * NN * M + (size_t)rbase * M + col0 + wn;
#pragma unroll
            for (int n = 0; n < 4; n++)
                wmma::store_matrix_sync(op + n * 16, acc[i][n], M, wmma::mem_row_major);
        }
    }
}

// ---------------- split conversion (elementwise; also used for W in native layout) --------------
__global__ void split_kernel(const float* __restrict__ in, __nv_bfloat16* __restrict__ hi,
                             __nv_bfloat16* __restrict__ lo, int n4) {
    int i = blockIdx.x * blockDim.x + threadIdx.x;
    if (i >= n4) return;
    float4 v = ((const float4*)in)[i];
    float a0 = v.x, a1 = v.y, a2 = v.z, a3 = v.w;
    __nv_bfloat16 h0 = __float2bfloat16(a0);
    __nv_bfloat16 h1 = __float2bfloat16(a1);
    __nv_bfloat16 h2 = __float2bfloat16(a2);
    __nv_bfloat16 h3 = __float2bfloat16(a3);
    hi[i * 4 + 0] = h0; hi[i * 4 + 1] = h1; hi[i * 4 + 2] = h2; hi[i * 4 + 3] = h3;
    lo[i * 4 + 0] = __float2bfloat16(a0 - __bfloat162float(h0));
    lo[i * 4 + 1] = __float2bfloat16(a1 - __bfloat162float(h1));
    lo[i * 4 + 2] = __float2bfloat16(a2 - __bfloat162float(h2));
    lo[i * 4 + 3] = __float2bfloat16(a3 - __bfloat162float(h3));
}

// ---------------- per-node attention logits ----------------
template <int H, int C>
__global__ void al_kernel(const float* __restrict__ hbuf, const float* __restrict__ a_src,
                          const float* __restrict__ a_dst, float* __restrict__ als,
                          float* __restrict__ ald) {
    int idx = blockIdx.x * blockDim.x + threadIdx.x;
    if (idx >= G * NN * H) return;
    int h = idx % H;
    int gn = idx / H;
    int g = gn / NN;
    const float* hp = hbuf + (size_t)gn * (H * C) + h * C;
    const float* as = a_src + (g * H + h) * C;
    const float* ad = a_dst + (g * H + h) * C;
    float s1 = 0.f, s2 = 0.f;
#pragma unroll
    for (int c = 0; c < C; c += 4) {
        float4 hv = *(const float4*)(hp + c);
        float4 av = *(const float4*)(as + c);
        float4 dv = *(const float4*)(ad + c);
        s1 += hv.x * av.x + hv.y * av.y + hv.z * av.z + hv.w * av.w;
        s2 += hv.x * dv.x + hv.y * dv.y + hv.z * dv.z + hv.w * dv.w;
    }
    als[idx] = s1;
    ald[idx] = s2;
}

// ---------------- CSR build ----------------
__global__ void csr_zero_kernel() {
    int i = blockIdx.x * blockDim.x + threadIdx.x;
    if (i < M_NODES) g_cnt[i] = 0;
}
__global__ void csr_hist_kernel(const int* __restrict__ ei) {
    int idx = blockIdx.x * blockDim.x + threadIdx.x;
    if (idx >= G * NE) return;
    int g = idx / NE, e = idx % NE;
    int dst = ei[(size_t)g * 2 * NE + NE + e];
    atomicAdd(&g_cnt[g * NN + dst], 1);
}
__global__ void csr_scanA_kernel() {
    __shared__ int sh[SCAN_BLK];
    int i = blockIdx.x * SCAN_BLK + threadIdx.x;
    int v = (i < M_NODES) ? g_cnt[i] : 0;
    sh[threadIdx.x] = v;
    __syncthreads();
#pragma unroll
    for (int off = 1; off < SCAN_BLK; off <<= 1) {
        int t = (threadIdx.x >= off) ? sh[threadIdx.x - off] : 0;
        __syncthreads();
        sh[threadIdx.x] += t;
        __syncthreads();
    }
    if (i < M_NODES) g_rowptr[i] = sh[threadIdx.x] - v;
    if (threadIdx.x == SCAN_BLK - 1) g_bsum[blockIdx.x] = sh[SCAN_BLK - 1];
}
__global__ void csr_scanB_kernel() {
    __shared__ int sh[128];
    int t = threadIdx.x;
    int v = (t < NBLK) ? g_bsum[t] : 0;
    sh[t] = v;
    __syncthreads();
#pragma unroll
    for (int off = 1; off < 128; off <<= 1) {
        int u = (t >= off) ? sh[t - off] : 0;
        __syncthreads();
        sh[t] += u;
        __syncthreads();
    }
    if (t < NBLK) g_bpre[t] = sh[t] - v;
    if (t == 127) g_rowptr[M_NODES] = sh[127];
}
__global__ void csr_scanC_kernel() {
    int i = blockIdx.x * blockDim.x + threadIdx.x;
    if (i >= M_NODES) return;
    int v = g_rowptr[i] + g_bpre[i / SCAN_BLK];
    g_rowptr[i] = v;
    g_fill[i] = v;
}
__global__ void csr_scatter_kernel(const int* __restrict__ ei) {
    int idx = blockIdx.x * blockDim.x + threadIdx.x;
    if (idx >= G * NE) return;
    int g = idx / NE, e = idx % NE;
    int src = ei[(size_t)g * 2 * NE + e];
    int dst = ei[(size_t)g * 2 * NE + NE + e];
    int pos = atomicAdd(&g_fill[g * NN + dst], 1);
    g_col[pos] = src;
}

// ---------------- fused online-softmax + aggregation + bias + ELU (warp per dst node) ----------
__device__ __forceinline__ float lrelu(float v) { return v > 0.f ? v : 0.2f * v; }

template <int H, int C, int SPLIT>
__global__ void node_agg_kernel(const float* __restrict__ als, const float* __restrict__ ald,
                                const float* __restrict__ hbuf, const float* __restrict__ bias,
                                float* __restrict__ outf, __nv_bfloat16* __restrict__ ohi,
                                __nv_bfloat16* __restrict__ olo) {
    int wid = (blockIdx.x * blockDim.x + threadIdx.x) >> 5;
    int lane = threadIdx.x & 31;
    if (wid >= M_NODES) return;
    int g = wid / NN;
    const int gbase = g * NN;

    int rbeg = g_rowptr[wid];
    int deg = g_rowptr[wid + 1] - rbeg;

    float aldh[H], m[H], s[H];
#pragma unroll
    for (int h = 0; h < H; h++) {
        aldh[h] = ald[wid * H + h];
        float selfv = lrelu(als[wid * H + h] + aldh[h]);
        m[h] = (lane == 0) ? selfv : -1e30f;
        s[h] = (lane == 0) ? 1.f : 0.f;
    }
    for (int i = lane; i < deg; i += 32) {
        int src = g_col[rbeg + i];
#pragma unroll
        for (int h = 0; h < H; h++) {
            float e = lrelu(als[(gbase + src) * H + h] + aldh[h]);
            float mn = fmaxf(m[h], e);
            s[h] = s[h] * __expf(m[h] - mn) + __expf(e - mn);
            m[h] = mn;
        }
    }
#pragma unroll
    for (int h = 0; h < H; h++) {
#pragma unroll
        for (int off = 16; off > 0; off >>= 1) {
            float mo = __shfl_xor_sync(0xFFFFFFFFu, m[h], off);
            float so = __shfl_xor_sync(0xFFFFFFFFu, s[h], off);
            float mn = fmaxf(m[h], mo);
            s[h] = s[h] * __expf(m[h] - mn) + so * __expf(mo - mn);
            m[h] = mn;
        }
    }

    constexpr int F = H * C;
    constexpr int PER = F / 32;
    const int f0 = lane * PER;
    const int myh = f0 / C;
    const float inv_s = 1.f / s[myh];
    const float mymx = m[myh];
    const float myald = aldh[myh];

    float acc[PER];
    {
        float selfv = lrelu(als[wid * H + myh] + myald);
        float a_self = __expf(selfv - mymx) * inv_s;
        const float* hp = hbuf + (size_t)wid * F + f0;
#pragma unroll
        for (int c = 0; c < PER; c += 4) {
            float4 v = *(const float4*)(hp + c);
            acc[c + 0] = v.x * a_self;
            acc[c + 1] = v.y * a_self;
            acc[c + 2] = v.z * a_self;
            acc[c + 3] = v.w * a_self;
        }
    }
    for (int i = 0; i < deg; i++) {
        int src = g_col[rbeg + i];
        float alpha = __expf(lrelu(als[(gbase + src) * H + myh] + myald) - mymx) * inv_s;
        const float* hp = hbuf + (size_t)(gbase + src) * F + f0;
#pragma unroll
        for (int c = 0; c < PER; c += 4) {
            float4 v = *(const float4*)(hp + c);
            acc[c + 0] += v.x * alpha;
            acc[c + 1] += v.y * alpha;
            acc[c + 2] += v.z * alpha;
            acc[c + 3] += v.w * alpha;
        }
    }
    const float* bp = bias + g * F + f0;
    if (SPLIT) {
        __nv_bfloat16* hp2 = ohi + (size_t)wid * F + f0;
        __nv_bfloat16* lp2 = olo + (size_t)wid * F + f0;
#pragma unroll
        for (int c = 0; c < PER; c++) {
            float v = acc[c] + bp[c];
            v = v > 0.f ? v : expm1f(v);
            __nv_bfloat16 h = __float2bfloat16(v);
            hp2[c] = h;
            lp2[c] = __float2bfloat16(v - __bfloat162float(h));
        }
    } else {
        float* op = outf + (size_t)wid * F + f0;
#pragma unroll
        for (int c = 0; c < PER; c++) {
            float v = acc[c] + bp[c];
            op[c] = v > 0.f ? v : expm1f(v);
        }
    }
}

// ---------------- host ----------------
static inline int ceil_div(int a, int b) { return (a + b - 1) / b; }

extern "C" void kernel_launch(void* const* d_in, const int* in_sizes, int n_in,
                              void* d_out, int out_size) {
    const float* x   = (const float*)d_in[0];
    const int*   ei  = (const int*)d_in[1];
    const float* W1  = (const float*)d_in[2];
    const float* a1s = (const float*)d_in[3];
    const float* a1d = (const float*)d_in[4];
    const float* b1  = (const float*)d_in[5];
    const float* W2  = (const float*)d_in[6];
    const float* a2s = (const float*)d_in[7];
    const float* a2d = (const float*)d_in[8];
    const float* b2  = (const float*)d_in[9];
    float* out = (float*)d_out;

    float *h1, *h2, *als, *ald;
    __nv_bfloat16 *xhi, *xlo, *a1hi, *a1lo, *w1hi, *w1lo, *w2hi, *w2lo;
    cudaGetSymbolAddress((void**)&h1, g_h1);
    cudaGetSymbolAddress((void**)&h2, g_h2);
    cudaGetSymbolAddress((void**)&als, g_als);
    cudaGetSymbolAddress((void**)&ald, g_ald);
    cudaGetSymbolAddress((void**)&xhi, g_xhi);
    cudaGetSymbolAddress((void**)&xlo, g_xlo);
    cudaGetSymbolAddress((void**)&a1hi, g_a1hi);
    cudaGetSymbolAddress((void**)&a1lo, g_a1lo);
    cudaGetSymbolAddress((void**)&w1hi, g_w1hi);
    cudaGetSymbolAddress((void**)&w1lo, g_w1lo);
    cudaGetSymbolAddress((void**)&w2hi, g_w2hi);
    cudaGetSymbolAddress((void**)&w2lo, g_w2lo);

    cudaFuncSetAttribute(gemm_wmma_kernel<128, 256>,
                         cudaFuncAttributeMaxDynamicSharedMemorySize, SMEM_TOT);
    cudaFuncSetAttribute(gemm_wmma_kernel<256, 128>,
                         cudaFuncAttributeMaxDynamicSharedMemorySize, SMEM_TOT);

    const int TPB = 256;
    const int nrow_blocks = ceil_div(NN, 128);  // 391

    // conversions first, gemm1 as the 4th launch (ncu capture window)
    split_kernel<<<ceil_div(G * NN * 128 / 4, TPB), TPB>>>(x, xhi, xlo, G * NN * 128 / 4);
    split_kernel<<<ceil_div(G * 128 * 256 / 4, TPB), TPB>>>(W1, w1hi, w1lo, G * 128 * 256 / 4);
    split_kernel<<<ceil_div(G * 256 * 128 / 4, TPB), TPB>>>(W2, w2hi, w2lo, G * 256 * 128 / 4);
    gemm_wmma_kernel<128, 256><<<dim3(nrow_blocks, 2, G), TPB, SMEM_TOT>>>(xhi, xlo, w1hi, w1lo, h1);

    // CSR build (shared by both layers)
    csr_zero_kernel<<<ceil_div(M_NODES, TPB), TPB>>>();
    csr_hist_kernel<<<ceil_div(G * NE, TPB), TPB>>>(ei);
    csr_scanA_kernel<<<NBLK, SCAN_BLK>>>();
    csr_scanB_kernel<<<1, 128>>>();
    csr_scanC_kernel<<<ceil_div(M_NODES, TPB), TPB>>>();
    csr_scatter_kernel<<<ceil_div(G * NE, TPB), TPB>>>(ei);

    // ---- Layer 1: heads=4, C=64 ----
    al_kernel<4, 64><<<ceil_div(G * NN * 4, TPB), TPB>>>(h1, a1s, a1d, als, ald);
    node_agg_kernel<4, 64, 1><<<ceil_div(M_NODES * 32, TPB), TPB>>>(als, ald, h1, b1,
                                                                    (float*)0, a1hi, a1lo);

    // ---- Layer 2: heads=1, C=128 ----
    gemm_wmma_kernel<256, 128><<<dim3(nrow_blocks, 1, G), TPB, SMEM_TOT>>>(a1hi, a1lo, w2hi, w2lo, h2);
    al_kernel<1, 128><<<ceil_div(G * NN, TPB), TPB>>>(h2, a2s, a2d, als, ald);
    node_agg_kernel<1, 128, 0><<<ceil_div(M_NODES * 32, TPB), TPB>>>(als, ald, h2, b2,
                                                                     out, (__nv_bfloat16*)0,
                                                                     (__nv_bfloat16*)0);
}